// round 13
// baseline (speedup 1.0000x reference)
#include <cuda_runtime.h>
#include <cuda_fp16.h>
#include <math.h>
#include <stdint.h>

// Problem constants
#define S_LEN 4096
#define BATCH 4
#define DM    1024
#define MTOT  (BATCH * S_LEN)

#define KS     32
#define NSLAB  (DM / KS)       // 32
#define APITCH 40              // smem row pitch in halves (+8 pad)

// All GEMMs: CTA 128x128, 256 thr (8 warps, 4m x 2n), warp 32x64, 2 CTA/SM.
#define STG_HALVES ((256 + 256) * APITCH)          // 20480
#define GEMM_SMEM  (2 * STG_HALVES * 2)            // 81920 B

#define MK_SLICES 4
#define MK_SLABS  (NSLAB / MK_SLICES)              // 8 slabs per K-slice

// ---------------------------------------------------------------------------
// Scratch (device globals)
// ---------------------------------------------------------------------------
__device__ __half g_x1h[(size_t)MTOT * DM];   // hidden split
__device__ __half g_x1l[(size_t)MTOT * DM];
__device__ __half g_x2h[(size_t)MTOT * DM];   // hidden+pre split
__device__ __half g_x2l[(size_t)MTOT * DM];
__device__ __half g_w1h[(size_t)DM * DM];     // w1 split, row-major [d][e]
__device__ __half g_w1l[(size_t)DM * DM];
__device__ __half g_w2h[(size_t)DM * DM];     // w2 split, row-major [d][e]
__device__ __half g_w2l[(size_t)DM * DM];
__device__ float  g_mp[(size_t)MK_SLICES * DM * DM];  // M split-K partials
__device__ __half g_mh[(size_t)DM * DM];      // M = w1 w2^T split, [d][d']
__device__ __half g_ml[(size_t)DM * DM];
__device__ __half g_th[(size_t)MTOT * DM];    // T = X2 M^T split, [k][d]
__device__ __half g_tl[(size_t)MTOT * DM];
__device__ float  g_u[DM];                    // u = w2 b1
__device__ float  g_v2[MTOT];                 // v2 = (hidden+pre) . u

// ---------------------------------------------------------------------------
// PTX helpers
// ---------------------------------------------------------------------------
__device__ __forceinline__ uint32_t smem_u32(const void* p) {
    return (uint32_t)__cvta_generic_to_shared(p);
}
__device__ __forceinline__ void ldsm4(uint32_t addr, uint32_t& r0, uint32_t& r1,
                                      uint32_t& r2, uint32_t& r3) {
    asm volatile("ldmatrix.sync.aligned.m8n8.x4.shared.b16 {%0,%1,%2,%3}, [%4];\n"
                 : "=r"(r0), "=r"(r1), "=r"(r2), "=r"(r3) : "r"(addr));
}
__device__ __forceinline__ void mma16816(float c[4], const uint32_t a[4],
                                         uint32_t b0, uint32_t b1) {
    asm volatile(
        "mma.sync.aligned.m16n8k16.row.col.f32.f16.f16.f32 "
        "{%0,%1,%2,%3}, {%4,%5,%6,%7}, {%8,%9}, {%0,%1,%2,%3};\n"
        : "+f"(c[0]), "+f"(c[1]), "+f"(c[2]), "+f"(c[3])
        : "r"(a[0]), "r"(a[1]), "r"(a[2]), "r"(a[3]), "r"(b0), "r"(b1));
}
__device__ __forceinline__ void cp16(void* sdst, const void* gsrc) {
    uint32_t s = smem_u32(sdst);
    asm volatile("cp.async.cg.shared.global [%0], [%1], 16;\n" :: "r"(s), "l"(gsrc));
}
#define CP_COMMIT() asm volatile("cp.async.commit_group;\n" ::: "memory")
#define CP_WAIT1()  asm volatile("cp.async.wait_group 1;\n" ::: "memory")
#define CP_WAIT0()  asm volatile("cp.async.wait_group 0;\n" ::: "memory")

// ---------------------------------------------------------------------------
// Kernel 1: u[d] = sum_e w2[d,e] * b1[e]   (warp per row)
// ---------------------------------------------------------------------------
__global__ __launch_bounds__(256) void u_kernel(
    const float* __restrict__ w2, const float* __restrict__ b1) {
    const int warp = threadIdx.x >> 5, lane = threadIdx.x & 31;
    const int row = blockIdx.x * 8 + warp;
    const float* p = w2 + (size_t)row * DM;
    float s = 0.f;
#pragma unroll
    for (int j = 0; j < DM / 32; j++) s += p[lane + 32 * j] * b1[lane + 32 * j];
#pragma unroll
    for (int o = 16; o >= 1; o >>= 1) s += __shfl_xor_sync(0xffffffffu, s, o);
    if (lane == 0) g_u[row] = s;
}

// ---------------------------------------------------------------------------
// Kernel 2a: split hidden+pre -> x2 hi/lo (critical path: feeds T-gemm)
// ---------------------------------------------------------------------------
__global__ __launch_bounds__(256) void split_x2_kernel(
    const float* __restrict__ hidden, const float* __restrict__ pre) {
    size_t i = ((size_t)blockIdx.x * 256 + threadIdx.x) * 4;
    float4 hv = *(const float4*)(hidden + i);
    float4 pv = *(const float4*)(pre + i);
    float x2[4] = {hv.x + pv.x, hv.y + pv.y, hv.z + pv.z, hv.w + pv.w};
    __half h2[4], l2[4];
#pragma unroll
    for (int j = 0; j < 4; j++) {
        h2[j] = __float2half_rn(x2[j]);
        l2[j] = __float2half_rn(x2[j] - __half2float(h2[j]));
    }
#pragma unroll
    for (int j = 0; j < 2; j++) {
        *(__half2*)(g_x2h + i + 2 * j) = __halves2half2(h2[2 * j], h2[2 * j + 1]);
        *(__half2*)(g_x2l + i + 2 * j) = __halves2half2(l2[2 * j], l2[2 * j + 1]);
    }
}

// ---------------------------------------------------------------------------
// Kernel 2b: split hidden -> x1 hi/lo (feeds gemm2 only; overlaps T-gemm)
// ---------------------------------------------------------------------------
__global__ __launch_bounds__(256) void split_x1_kernel(
    const float* __restrict__ hidden) {
    size_t i = ((size_t)blockIdx.x * 256 + threadIdx.x) * 4;
    float4 hv = *(const float4*)(hidden + i);
    float x1[4] = {hv.x, hv.y, hv.z, hv.w};
    __half h1[4], l1[4];
#pragma unroll
    for (int j = 0; j < 4; j++) {
        h1[j] = __float2half_rn(x1[j]);
        l1[j] = __float2half_rn(x1[j] - __half2float(h1[j]));
    }
#pragma unroll
    for (int j = 0; j < 2; j++) {
        *(__half2*)(g_x1h + i + 2 * j) = __halves2half2(h1[2 * j], h1[2 * j + 1]);
        *(__half2*)(g_x1l + i + 2 * j) = __halves2half2(l1[2 * j], l1[2 * j + 1]);
    }
}

// ---------------------------------------------------------------------------
// Kernel 2c: v2[r] = (hidden[r]+pre[r]) . u   (warp per row; feeds softmax)
// ---------------------------------------------------------------------------
__global__ __launch_bounds__(256) void v2_kernel(
    const float* __restrict__ hidden, const float* __restrict__ pre) {
    const int warp = threadIdx.x >> 5, lane = threadIdx.x & 31;
    const int row = blockIdx.x * 8 + warp;
    const float* ph = hidden + (size_t)row * DM;
    const float* pp = pre + (size_t)row * DM;
    float s = 0.f;
#pragma unroll
    for (int j = 0; j < DM / 32; j++) {
        int d = lane + 32 * j;
        s += (ph[d] + pp[d]) * g_u[d];
    }
#pragma unroll
    for (int o = 16; o >= 1; o >>= 1) s += __shfl_xor_sync(0xffffffffu, s, o);
    if (lane == 0) g_v2[row] = s;
}

// ---------------------------------------------------------------------------
// Kernel 3: elementwise split of w1, w2 (row-major, no transpose)
// ---------------------------------------------------------------------------
__global__ __launch_bounds__(256) void split_w_kernel(
    const float* __restrict__ w1, const float* __restrict__ w2) {
    size_t i = ((size_t)blockIdx.x * 256 + threadIdx.x) * 4;
    float4 v1 = *(const float4*)(w1 + i);
    float4 v2 = *(const float4*)(w2 + i);
    float a1[4] = {v1.x, v1.y, v1.z, v1.w};
    float a2[4] = {v2.x, v2.y, v2.z, v2.w};
#pragma unroll
    for (int j = 0; j < 4; j++) {
        __half h1 = __float2half_rn(a1[j]);
        __half h2 = __float2half_rn(a2[j]);
        g_w1h[i + j] = h1; g_w1l[i + j] = __float2half_rn(a1[j] - __half2float(h1));
        g_w2h[i + j] = h2; g_w2l[i + j] = __float2half_rn(a2[j] - __half2float(h2));
    }
}

// ---------------------------------------------------------------------------
// Shared rows-x-rows mainloop: acc[2][8][4] += split-fp16 x3 of
//   C[m,n] = sum_{k in [kbeg, kbeg+kcnt*KS)} A[bm+m, k] * B[bn+n, k]
// ---------------------------------------------------------------------------
__device__ __forceinline__ void mainloop(
    __half* sm, const __half* __restrict__ Ah, const __half* __restrict__ Al,
    const __half* __restrict__ Bh, const __half* __restrict__ Bl,
    int bm, int bn, int kbeg, int kcnt,
    int tid, int wm, int wn, int lane, float acc[2][8][4])
{
    constexpr int ST_AH = 0;
    constexpr int ST_AL = 128 * APITCH;
    constexpr int ST_BH = 256 * APITCH;
    constexpr int ST_BL = 384 * APITCH;

    auto load_slab = [&](int k0, int s) {
        __half* stg = sm + s * STG_HALVES;
#pragma unroll
        for (int t = 0; t < 2; t++) {
            int slot = tid + t * 256;
            int row = slot >> 2, cg = slot & 3;
            int so = row * APITCH + cg * 8;
            size_t ga = (size_t)(bm + row) * DM + k0 + cg * 8;
            size_t gb = (size_t)(bn + row) * DM + k0 + cg * 8;
            cp16(stg + ST_AH + so, Ah + ga);
            cp16(stg + ST_AL + so, Al + ga);
            cp16(stg + ST_BH + so, Bh + gb);
            cp16(stg + ST_BL + so, Bl + gb);
        }
        CP_COMMIT();
    };

    load_slab(kbeg, 0);

    for (int i = 0; i < kcnt; i++) {
        const int s = i & 1;
        if (i + 1 < kcnt) { load_slab(kbeg + (i + 1) * KS, s ^ 1); CP_WAIT1(); }
        else              { CP_WAIT0(); }
        __syncthreads();

        const __half* stg = sm + s * STG_HALVES;
        const __half* sAh = stg + ST_AH;
        const __half* sAl = stg + ST_AL;
        const __half* sBh = stg + ST_BH;
        const __half* sBl = stg + ST_BL;
        const int g = lane >> 3;

#pragma unroll
        for (int kk = 0; kk < KS; kk += 16) {
            const int col = kk + (g >> 1) * 8;
            uint32_t ah[2][4], al[2][4];
#pragma unroll
            for (int mi = 0; mi < 2; mi++) {
                int row = wm * 32 + mi * 16 + (lane & 7) + (g & 1) * 8;
                ldsm4(smem_u32(sAh + row * APITCH + col),
                      ah[mi][0], ah[mi][1], ah[mi][2], ah[mi][3]);
                ldsm4(smem_u32(sAl + row * APITCH + col),
                      al[mi][0], al[mi][1], al[mi][2], al[mi][3]);
            }
            uint32_t bh[4][4];
#pragma unroll
            for (int ng = 0; ng < 4; ng++) {
                int row = wn * 64 + ng * 16 + (lane & 7) + (g & 1) * 8;
                ldsm4(smem_u32(sBh + row * APITCH + col),
                      bh[ng][0], bh[ng][1], bh[ng][2], bh[ng][3]);
            }
#pragma unroll
            for (int ng = 0; ng < 4; ng++)
#pragma unroll
                for (int mi = 0; mi < 2; mi++) {
                    mma16816(acc[mi][2 * ng],     ah[mi], bh[ng][0], bh[ng][2]);
                    mma16816(acc[mi][2 * ng + 1], ah[mi], bh[ng][1], bh[ng][3]);
                }
#pragma unroll
            for (int ng = 0; ng < 4; ng++)
#pragma unroll
                for (int mi = 0; mi < 2; mi++) {
                    mma16816(acc[mi][2 * ng],     al[mi], bh[ng][0], bh[ng][2]);
                    mma16816(acc[mi][2 * ng + 1], al[mi], bh[ng][1], bh[ng][3]);
                }
#pragma unroll
            for (int ng = 0; ng < 4; ng++) {
                int row = wn * 64 + ng * 16 + (lane & 7) + (g & 1) * 8;
                uint32_t r0, r1, r2, r3;
                ldsm4(smem_u32(sBl + row * APITCH + col), r0, r1, r2, r3);
#pragma unroll
                for (int mi = 0; mi < 2; mi++) {
                    mma16816(acc[mi][2 * ng],     ah[mi], r0, r2);
                    mma16816(acc[mi][2 * ng + 1], ah[mi], r1, r3);
                }
            }
        }
        __syncthreads();
    }
}

// ---------------------------------------------------------------------------
// Kernel 4: gemm_partial — fp32 partial C for one K-slice (split-K M-gemm).
// ---------------------------------------------------------------------------
__global__ __launch_bounds__(256, 2) void gemm_partial_kernel(
    const __half* __restrict__ Ah, const __half* __restrict__ Al,
    const __half* __restrict__ Bh, const __half* __restrict__ Bl) {
    extern __shared__ __half sm[];
    const int tid = threadIdx.x, lane = tid & 31, warp = tid >> 5;
    const int wm = warp >> 1, wn = warp & 1;
    const int bm = blockIdx.y * 128, bn = blockIdx.x * 128;
    const int slice = blockIdx.z;

    float acc[2][8][4];
#pragma unroll
    for (int mi = 0; mi < 2; mi++)
#pragma unroll
        for (int ni = 0; ni < 8; ni++)
#pragma unroll
            for (int j = 0; j < 4; j++) acc[mi][ni][j] = 0.f;

    mainloop(sm, Ah, Al, Bh, Bl, bm, bn, slice * (MK_SLABS * KS), MK_SLABS,
             tid, wm, wn, lane, acc);

    float* Cp = g_mp + (size_t)slice * DM * DM;
#pragma unroll
    for (int mi = 0; mi < 2; mi++) {
#pragma unroll
        for (int ni = 0; ni < 8; ni++) {
            int col = bn + wn * 64 + ni * 8 + 2 * (lane & 3);
#pragma unroll
            for (int h = 0; h < 2; h++) {
                int row = bm + wm * 32 + mi * 16 + (lane >> 2) + h * 8;
                *(float2*)(Cp + (size_t)row * DM + col) =
                    make_float2(acc[mi][ni][2 * h + 0], acc[mi][ni][2 * h + 1]);
            }
        }
    }
}

// ---------------------------------------------------------------------------
// Kernel 5: reduce 4 fp32 partials -> M, split to fp16 hi/lo
// ---------------------------------------------------------------------------
__global__ __launch_bounds__(256) void reduce_split_kernel() {
    size_t i = ((size_t)blockIdx.x * 256 + threadIdx.x) * 4;
    float4 a = *(const float4*)(g_mp + i);
    float4 b = *(const float4*)(g_mp + (size_t)DM * DM + i);
    float4 c = *(const float4*)(g_mp + 2 * (size_t)DM * DM + i);
    float4 d = *(const float4*)(g_mp + 3 * (size_t)DM * DM + i);
    float v[4] = {a.x + b.x + c.x + d.x, a.y + b.y + c.y + d.y,
                  a.z + b.z + c.z + d.z, a.w + b.w + c.w + d.w};
    __half hh[4], ll[4];
#pragma unroll
    for (int j = 0; j < 4; j++) {
        hh[j] = __float2half_rn(v[j]);
        ll[j] = __float2half_rn(v[j] - __half2float(hh[j]));
    }
#pragma unroll
    for (int j = 0; j < 2; j++) {
        *(__half2*)(g_mh + i + 2 * j) = __halves2half2(hh[2 * j], hh[2 * j + 1]);
        *(__half2*)(g_ml + i + 2 * j) = __halves2half2(ll[2 * j], ll[2 * j + 1]);
    }
}

// ---------------------------------------------------------------------------
// Kernel 6: gemm_split — C = A-rows . B-rows, epilogue re-splits to fp16 hi/lo.
// Used for T = X2.M^T (grid 8x128).
// ---------------------------------------------------------------------------
__global__ __launch_bounds__(256, 2) void gemm_split_kernel(
    const __half* __restrict__ Ah, const __half* __restrict__ Al,
    const __half* __restrict__ Bh, const __half* __restrict__ Bl,
    __half* __restrict__ Ch, __half* __restrict__ Cl) {
    extern __shared__ __half sm[];
    const int tid = threadIdx.x, lane = tid & 31, warp = tid >> 5;
    const int wm = warp >> 1, wn = warp & 1;
    const int bm = blockIdx.y * 128, bn = blockIdx.x * 128;

    float acc[2][8][4];
#pragma unroll
    for (int mi = 0; mi < 2; mi++)
#pragma unroll
        for (int ni = 0; ni < 8; ni++)
#pragma unroll
            for (int j = 0; j < 4; j++) acc[mi][ni][j] = 0.f;

    mainloop(sm, Ah, Al, Bh, Bl, bm, bn, 0, NSLAB, tid, wm, wn, lane, acc);

#pragma unroll
    for (int mi = 0; mi < 2; mi++) {
#pragma unroll
        for (int ni = 0; ni < 8; ni++) {
            int col = bn + wn * 64 + ni * 8 + 2 * (lane & 3);
#pragma unroll
            for (int h = 0; h < 2; h++) {
                int row = bm + wm * 32 + mi * 16 + (lane >> 2) + h * 8;
                float v0 = acc[mi][ni][2 * h + 0];
                float v1 = acc[mi][ni][2 * h + 1];
                __half h0 = __float2half_rn(v0), h1 = __float2half_rn(v1);
                __half l0 = __float2half_rn(v0 - __half2float(h0));
                __half l1 = __float2half_rn(v1 - __half2float(h1));
                *(__half2*)(Ch + (size_t)row * DM + col) = __halves2half2(h0, h1);
                *(__half2*)(Cl + (size_t)row * DM + col) = __halves2half2(l0, l1);
            }
        }
    }
}

// ---------------------------------------------------------------------------
// Kernel 7: gemm2 — logits[q,k] = X-rows . T-rows per batch -> d_out (fp32)
// ---------------------------------------------------------------------------
__global__ __launch_bounds__(256, 2) void gemm2_kernel(float* __restrict__ out) {
    extern __shared__ __half sm[];
    const int tid = threadIdx.x, lane = tid & 31, warp = tid >> 5;
    const int wm = warp >> 1, wn = warp & 1;
    const int bq = blockIdx.y * 128, bk = blockIdx.x * 128;
    const int bat = blockIdx.z;

    const __half* Ah = g_x1h + (size_t)bat * S_LEN * DM;
    const __half* Al = g_x1l + (size_t)bat * S_LEN * DM;
    const __half* Bh = g_th + (size_t)bat * S_LEN * DM;
    const __half* Bl = g_tl + (size_t)bat * S_LEN * DM;

    float acc[2][8][4];
#pragma unroll
    for (int mi = 0; mi < 2; mi++)
#pragma unroll
        for (int ni = 0; ni < 8; ni++)
#pragma unroll
            for (int j = 0; j < 4; j++) acc[mi][ni][j] = 0.f;

    mainloop(sm, Ah, Al, Bh, Bl, bq, bk, 0, NSLAB, tid, wm, wn, lane, acc);

    float* obase = out + (size_t)bat * S_LEN * S_LEN;
#pragma unroll
    for (int mi = 0; mi < 2; mi++) {
#pragma unroll
        for (int ni = 0; ni < 8; ni++) {
            int col = bk + wn * 64 + ni * 8 + 2 * (lane & 3);
#pragma unroll
            for (int h = 0; h < 2; h++) {
                int row = bq + wm * 32 + mi * 16 + (lane >> 2) + h * 8;
                __stcs((float2*)(obase + (size_t)row * S_LEN + col),
                       make_float2(acc[mi][ni][2 * h + 0], acc[mi][ni][2 * h + 1]));
            }
        }
    }
}

// ---------------------------------------------------------------------------
// Kernel 8: rowwise softmax in place with v2[k] bias, streaming ld/st
// ---------------------------------------------------------------------------
__global__ __launch_bounds__(256) void softmax_kernel(float* __restrict__ out) {
    __shared__ float red[8];
    const int t = threadIdx.x, lane = t & 31, warp = t >> 5;
    const int rowg = blockIdx.x;
    float* p = out + (size_t)rowg * S_LEN;
    const float* v2p = g_v2 + (rowg & ~(S_LEN - 1));  // batch base

    float4 v[4];
#pragma unroll
    for (int i = 0; i < 4; i++) {
        int off = (i * 256 + t) * 4;
        float4 lv = __ldcs((const float4*)(p + off));
        float4 bv = *(const float4*)(v2p + off);
        v[i] = make_float4(lv.x + bv.x, lv.y + bv.y, lv.z + bv.z, lv.w + bv.w);
    }

    float mx = -INFINITY;
#pragma unroll
    for (int i = 0; i < 4; i++)
        mx = fmaxf(mx, fmaxf(fmaxf(v[i].x, v[i].y), fmaxf(v[i].z, v[i].w)));
#pragma unroll
    for (int o = 16; o >= 1; o >>= 1)
        mx = fmaxf(mx, __shfl_xor_sync(0xffffffffu, mx, o));
    if (lane == 0) red[warp] = mx;
    __syncthreads();
    float bmx = red[0];
#pragma unroll
    for (int w = 1; w < 8; w++) bmx = fmaxf(bmx, red[w]);
    __syncthreads();

    float sum = 0.f;
#pragma unroll
    for (int i = 0; i < 4; i++) {
        v[i].x = __expf(v[i].x - bmx); sum += v[i].x;
        v[i].y = __expf(v[i].y - bmx); sum += v[i].y;
        v[i].z = __expf(v[i].z - bmx); sum += v[i].z;
        v[i].w = __expf(v[i].w - bmx); sum += v[i].w;
    }
#pragma unroll
    for (int o = 16; o >= 1; o >>= 1)
        sum += __shfl_xor_sync(0xffffffffu, sum, o);
    if (lane == 0) red[warp] = sum;
    __syncthreads();
    float bsum = 0.f;
#pragma unroll
    for (int w = 0; w < 8; w++) bsum += red[w];

    float inv = 1.0f / bsum;
#pragma unroll
    for (int i = 0; i < 4; i++) {
        v[i].x *= inv; v[i].y *= inv; v[i].z *= inv; v[i].w *= inv;
        __stcs((float4*)(p + (i * 256 + t) * 4), v[i]);
    }
}

// ---------------------------------------------------------------------------
// Launch DAG:
//   main: split_x2 ─────────[wait s2]→ T-gemm ─[wait s3]→ gemm2 → softmax
//   s2:   split_w → M-partial → reduce
//   s3:   u → split_x1 → v2
// ---------------------------------------------------------------------------
extern "C" void kernel_launch(void* const* d_in, const int* in_sizes, int n_in,
                              void* d_out, int out_size) {
    (void)in_sizes; (void)n_in; (void)out_size;
    const float* hidden = (const float*)d_in[0];
    const float* pre    = (const float*)d_in[1];
    const float* w1     = (const float*)d_in[2];
    const float* b1     = (const float*)d_in[3];
    const float* w2     = (const float*)d_in[4];
    const float* b2     = (const float*)d_in[5];
    (void)b2;  // b2 terms are row-constant in softmax -> cancel
    float* out = (float*)d_out;

    static cudaStream_t s2 = nullptr, s3 = nullptr;
    static cudaEvent_t ev_fork = nullptr, ev_m = nullptr, ev_x1 = nullptr;
    if (s2 == nullptr) {
        cudaStreamCreateWithFlags(&s2, cudaStreamNonBlocking);
        cudaStreamCreateWithFlags(&s3, cudaStreamNonBlocking);
        cudaEventCreateWithFlags(&ev_fork, cudaEventDisableTiming);
        cudaEventCreateWithFlags(&ev_m, cudaEventDisableTiming);
        cudaEventCreateWithFlags(&ev_x1, cudaEventDisableTiming);
    }

    cudaFuncSetAttribute(gemm_partial_kernel,
                         cudaFuncAttributeMaxDynamicSharedMemorySize, GEMM_SMEM);
    cudaFuncSetAttribute(gemm_split_kernel,
                         cudaFuncAttributeMaxDynamicSharedMemorySize, GEMM_SMEM);
    cudaFuncSetAttribute(gemm2_kernel,
                         cudaFuncAttributeMaxDynamicSharedMemorySize, GEMM_SMEM);

    __half *x2h, *x2l, *w1h, *w1l, *w2h, *w2l, *mh, *ml, *th, *tl;
    cudaGetSymbolAddress((void**)&x2h, g_x2h);
    cudaGetSymbolAddress((void**)&x2l, g_x2l);
    cudaGetSymbolAddress((void**)&w1h, g_w1h);
    cudaGetSymbolAddress((void**)&w1l, g_w1l);
    cudaGetSymbolAddress((void**)&w2h, g_w2h);
    cudaGetSymbolAddress((void**)&w2l, g_w2l);
    cudaGetSymbolAddress((void**)&mh, g_mh);
    cudaGetSymbolAddress((void**)&ml, g_ml);
    cudaGetSymbolAddress((void**)&th, g_th);
    cudaGetSymbolAddress((void**)&tl, g_tl);

    // Fork both side streams off the main stream head.
    cudaEventRecord(ev_fork, 0);
    cudaStreamWaitEvent(s2, ev_fork, 0);
    cudaStreamWaitEvent(s3, ev_fork, 0);

    // s2: weight split + M chain (independent of x data).
    split_w_kernel<<<(DM * DM) / (256 * 4), 256, 0, s2>>>(w1, w2);
    gemm_partial_kernel<<<dim3(DM / 128, DM / 128, MK_SLICES), 256, GEMM_SMEM, s2>>>(
        w1h, w1l, w2h, w2l);
    reduce_split_kernel<<<(DM * DM) / (256 * 4), 256, 0, s2>>>();
    cudaEventRecord(ev_m, s2);

    // s3: u -> x1 split -> v2 (consumers: gemm2, softmax; overlaps T-gemm).
    u_kernel<<<DM / 8, 256, 0, s3>>>(w2, b1);
    split_x1_kernel<<<(MTOT * DM) / (256 * 4), 256, 0, s3>>>(hidden);
    v2_kernel<<<MTOT / 8, 256, 0, s3>>>(hidden, pre);
    cudaEventRecord(ev_x1, s3);

    // main: x2 split (critical for T).
    split_x2_kernel<<<(MTOT * DM) / (256 * 4), 256>>>(hidden, pre);

    // Join M chain; T[k,d] = X2 rows . M rows.
    cudaStreamWaitEvent(0, ev_m, 0);
    gemm_split_kernel<<<dim3(DM / 128, MTOT / 128), 256, GEMM_SMEM>>>(
        x2h, x2l, mh, ml, th, tl);

    // Join x1/v2 chain; logits and softmax.
    cudaStreamWaitEvent(0, ev_x1, 0);
    gemm2_kernel<<<dim3(S_LEN / 128, S_LEN / 128, BATCH), 256, GEMM_SMEM>>>(out);
    softmax_kernel<<<MTOT, 256>>>(out);
}

// round 14
// speedup vs baseline: 1.0051x; 1.0051x over previous
#include <cuda_runtime.h>
#include <cuda_fp16.h>
#include <math.h>
#include <stdint.h>

// Problem constants
#define S_LEN 4096
#define BATCH 4
#define DM    1024
#define MTOT  (BATCH * S_LEN)

#define KS     32
#define NSLAB  (DM / KS)       // 32
#define APITCH 40              // smem row pitch in halves (+8 pad)

// All GEMMs: CTA 128x128, 256 thr (8 warps, 4m x 2n), warp 32x64, 2 CTA/SM.
#define STG_HALVES ((256 + 256) * APITCH)          // 20480
#define GEMM_SMEM  (2 * STG_HALVES * 2)            // 81920 B

#define MK_SLICES 4
#define MK_SLABS  (NSLAB / MK_SLICES)              // 8 slabs per K-slice

// ---------------------------------------------------------------------------
// Scratch (device globals)
// ---------------------------------------------------------------------------
__device__ __half g_x1h[(size_t)MTOT * DM];   // hidden split
__device__ __half g_x1l[(size_t)MTOT * DM];
__device__ __half g_x2h[(size_t)MTOT * DM];   // hidden+pre split
__device__ __half g_x2l[(size_t)MTOT * DM];
__device__ __half g_w1h[(size_t)DM * DM];     // w1 split, row-major [d][e]
__device__ __half g_w1l[(size_t)DM * DM];
__device__ __half g_w2h[(size_t)DM * DM];     // w2 split, row-major [d][e]
__device__ __half g_w2l[(size_t)DM * DM];
__device__ float  g_mp[(size_t)MK_SLICES * DM * DM];  // M split-K partials
__device__ __half g_mh[(size_t)DM * DM];      // M = w1 w2^T split, [d][d']
__device__ __half g_ml[(size_t)DM * DM];
__device__ __half g_th[(size_t)MTOT * DM];    // T = X2 M^T split, [k][d]
__device__ __half g_tl[(size_t)MTOT * DM];
__device__ float  g_u[DM];                    // u = w2 b1
__device__ float  g_v2[MTOT];                 // v2 = (hidden+pre) . u

// ---------------------------------------------------------------------------
// PTX helpers
// ---------------------------------------------------------------------------
__device__ __forceinline__ uint32_t smem_u32(const void* p) {
    return (uint32_t)__cvta_generic_to_shared(p);
}
__device__ __forceinline__ void ldsm4(uint32_t addr, uint32_t& r0, uint32_t& r1,
                                      uint32_t& r2, uint32_t& r3) {
    asm volatile("ldmatrix.sync.aligned.m8n8.x4.shared.b16 {%0,%1,%2,%3}, [%4];\n"
                 : "=r"(r0), "=r"(r1), "=r"(r2), "=r"(r3) : "r"(addr));
}
__device__ __forceinline__ void mma16816(float c[4], const uint32_t a[4],
                                         uint32_t b0, uint32_t b1) {
    asm volatile(
        "mma.sync.aligned.m16n8k16.row.col.f32.f16.f16.f32 "
        "{%0,%1,%2,%3}, {%4,%5,%6,%7}, {%8,%9}, {%0,%1,%2,%3};\n"
        : "+f"(c[0]), "+f"(c[1]), "+f"(c[2]), "+f"(c[3])
        : "r"(a[0]), "r"(a[1]), "r"(a[2]), "r"(a[3]), "r"(b0), "r"(b1));
}
__device__ __forceinline__ void cp16(void* sdst, const void* gsrc) {
    uint32_t s = smem_u32(sdst);
    asm volatile("cp.async.cg.shared.global [%0], [%1], 16;\n" :: "r"(s), "l"(gsrc));
}
#define CP_COMMIT() asm volatile("cp.async.commit_group;\n" ::: "memory")
#define CP_WAIT1()  asm volatile("cp.async.wait_group 1;\n" ::: "memory")
#define CP_WAIT0()  asm volatile("cp.async.wait_group 0;\n" ::: "memory")

// ---------------------------------------------------------------------------
// Kernel 1: u[d] = sum_e w2[d,e] * b1[e]   (warp per row)
// ---------------------------------------------------------------------------
__global__ __launch_bounds__(256) void u_kernel(
    const float* __restrict__ w2, const float* __restrict__ b1) {
    const int warp = threadIdx.x >> 5, lane = threadIdx.x & 31;
    const int row = blockIdx.x * 8 + warp;
    const float* p = w2 + (size_t)row * DM;
    float s = 0.f;
#pragma unroll
    for (int j = 0; j < DM / 32; j++) s += p[lane + 32 * j] * b1[lane + 32 * j];
#pragma unroll
    for (int o = 16; o >= 1; o >>= 1) s += __shfl_xor_sync(0xffffffffu, s, o);
    if (lane == 0) g_u[row] = s;
}

// ---------------------------------------------------------------------------
// Kernel 2: fused split of hidden -> x1 and hidden+pre -> x2 (one pass).
// No u/v2 dependency: runs immediately at launch.
// ---------------------------------------------------------------------------
__global__ __launch_bounds__(256) void split_x12_kernel(
    const float* __restrict__ hidden, const float* __restrict__ pre) {
    size_t i = ((size_t)blockIdx.x * 256 + threadIdx.x) * 4;
    float4 hv = *(const float4*)(hidden + i);
    float4 pv = *(const float4*)(pre + i);
    float x1[4] = {hv.x, hv.y, hv.z, hv.w};
    float x2[4] = {hv.x + pv.x, hv.y + pv.y, hv.z + pv.z, hv.w + pv.w};
    __half h1[4], l1[4], h2[4], l2[4];
#pragma unroll
    for (int j = 0; j < 4; j++) {
        h1[j] = __float2half_rn(x1[j]);
        l1[j] = __float2half_rn(x1[j] - __half2float(h1[j]));
        h2[j] = __float2half_rn(x2[j]);
        l2[j] = __float2half_rn(x2[j] - __half2float(h2[j]));
    }
#pragma unroll
    for (int j = 0; j < 2; j++) {
        *(__half2*)(g_x1h + i + 2 * j) = __halves2half2(h1[2 * j], h1[2 * j + 1]);
        *(__half2*)(g_x1l + i + 2 * j) = __halves2half2(l1[2 * j], l1[2 * j + 1]);
        *(__half2*)(g_x2h + i + 2 * j) = __halves2half2(h2[2 * j], h2[2 * j + 1]);
        *(__half2*)(g_x2l + i + 2 * j) = __halves2half2(l2[2 * j], l2[2 * j + 1]);
    }
}

// ---------------------------------------------------------------------------
// Kernel 3: v2[r] = (hidden[r]+pre[r]) . u  (warp per row; side stream,
// overlapped under the T-gemm; consumed only by softmax)
// ---------------------------------------------------------------------------
__global__ __launch_bounds__(256) void v2_kernel(
    const float* __restrict__ hidden, const float* __restrict__ pre) {
    const int warp = threadIdx.x >> 5, lane = threadIdx.x & 31;
    const int row = blockIdx.x * 8 + warp;
    const float* ph = hidden + (size_t)row * DM;
    const float* pp = pre + (size_t)row * DM;
    float s = 0.f;
#pragma unroll
    for (int j = 0; j < DM / 32; j++) {
        int d = lane + 32 * j;
        s += (ph[d] + pp[d]) * g_u[d];
    }
#pragma unroll
    for (int o = 16; o >= 1; o >>= 1) s += __shfl_xor_sync(0xffffffffu, s, o);
    if (lane == 0) g_v2[row] = s;
}

// ---------------------------------------------------------------------------
// Kernel 4: elementwise split of w1, w2 (row-major, no transpose)
// ---------------------------------------------------------------------------
__global__ __launch_bounds__(256) void split_w_kernel(
    const float* __restrict__ w1, const float* __restrict__ w2) {
    size_t i = ((size_t)blockIdx.x * 256 + threadIdx.x) * 4;
    float4 v1 = *(const float4*)(w1 + i);
    float4 v2 = *(const float4*)(w2 + i);
    float a1[4] = {v1.x, v1.y, v1.z, v1.w};
    float a2[4] = {v2.x, v2.y, v2.z, v2.w};
#pragma unroll
    for (int j = 0; j < 4; j++) {
        __half h1 = __float2half_rn(a1[j]);
        __half h2 = __float2half_rn(a2[j]);
        g_w1h[i + j] = h1; g_w1l[i + j] = __float2half_rn(a1[j] - __half2float(h1));
        g_w2h[i + j] = h2; g_w2l[i + j] = __float2half_rn(a2[j] - __half2float(h2));
    }
}

// ---------------------------------------------------------------------------
// Shared rows-x-rows mainloop: acc[2][8][4] += split-fp16 x3 of
//   C[m,n] = sum_{k in [kbeg, kbeg+kcnt*KS)} A[bm+m, k] * B[bn+n, k]
// ---------------------------------------------------------------------------
__device__ __forceinline__ void mainloop(
    __half* sm, const __half* __restrict__ Ah, const __half* __restrict__ Al,
    const __half* __restrict__ Bh, const __half* __restrict__ Bl,
    int bm, int bn, int kbeg, int kcnt,
    int tid, int wm, int wn, int lane, float acc[2][8][4])
{
    constexpr int ST_AH = 0;
    constexpr int ST_AL = 128 * APITCH;
    constexpr int ST_BH = 256 * APITCH;
    constexpr int ST_BL = 384 * APITCH;

    auto load_slab = [&](int k0, int s) {
        __half* stg = sm + s * STG_HALVES;
#pragma unroll
        for (int t = 0; t < 2; t++) {
            int slot = tid + t * 256;
            int row = slot >> 2, cg = slot & 3;
            int so = row * APITCH + cg * 8;
            size_t ga = (size_t)(bm + row) * DM + k0 + cg * 8;
            size_t gb = (size_t)(bn + row) * DM + k0 + cg * 8;
            cp16(stg + ST_AH + so, Ah + ga);
            cp16(stg + ST_AL + so, Al + ga);
            cp16(stg + ST_BH + so, Bh + gb);
            cp16(stg + ST_BL + so, Bl + gb);
        }
        CP_COMMIT();
    };

    load_slab(kbeg, 0);

    for (int i = 0; i < kcnt; i++) {
        const int s = i & 1;
        if (i + 1 < kcnt) { load_slab(kbeg + (i + 1) * KS, s ^ 1); CP_WAIT1(); }
        else              { CP_WAIT0(); }
        __syncthreads();

        const __half* stg = sm + s * STG_HALVES;
        const __half* sAh = stg + ST_AH;
        const __half* sAl = stg + ST_AL;
        const __half* sBh = stg + ST_BH;
        const __half* sBl = stg + ST_BL;
        const int g = lane >> 3;

#pragma unroll
        for (int kk = 0; kk < KS; kk += 16) {
            const int col = kk + (g >> 1) * 8;
            uint32_t ah[2][4], al[2][4];
#pragma unroll
            for (int mi = 0; mi < 2; mi++) {
                int row = wm * 32 + mi * 16 + (lane & 7) + (g & 1) * 8;
                ldsm4(smem_u32(sAh + row * APITCH + col),
                      ah[mi][0], ah[mi][1], ah[mi][2], ah[mi][3]);
                ldsm4(smem_u32(sAl + row * APITCH + col),
                      al[mi][0], al[mi][1], al[mi][2], al[mi][3]);
            }
            uint32_t bh[4][4];
#pragma unroll
            for (int ng = 0; ng < 4; ng++) {
                int row = wn * 64 + ng * 16 + (lane & 7) + (g & 1) * 8;
                ldsm4(smem_u32(sBh + row * APITCH + col),
                      bh[ng][0], bh[ng][1], bh[ng][2], bh[ng][3]);
            }
#pragma unroll
            for (int ng = 0; ng < 4; ng++)
#pragma unroll
                for (int mi = 0; mi < 2; mi++) {
                    mma16816(acc[mi][2 * ng],     ah[mi], bh[ng][0], bh[ng][2]);
                    mma16816(acc[mi][2 * ng + 1], ah[mi], bh[ng][1], bh[ng][3]);
                }
#pragma unroll
            for (int ng = 0; ng < 4; ng++)
#pragma unroll
                for (int mi = 0; mi < 2; mi++) {
                    mma16816(acc[mi][2 * ng],     al[mi], bh[ng][0], bh[ng][2]);
                    mma16816(acc[mi][2 * ng + 1], al[mi], bh[ng][1], bh[ng][3]);
                }
#pragma unroll
            for (int ng = 0; ng < 4; ng++) {
                int row = wn * 64 + ng * 16 + (lane & 7) + (g & 1) * 8;
                uint32_t r0, r1, r2, r3;
                ldsm4(smem_u32(sBl + row * APITCH + col), r0, r1, r2, r3);
#pragma unroll
                for (int mi = 0; mi < 2; mi++) {
                    mma16816(acc[mi][2 * ng],     ah[mi], r0, r2);
                    mma16816(acc[mi][2 * ng + 1], ah[mi], r1, r3);
                }
            }
        }
        __syncthreads();
    }
}

// ---------------------------------------------------------------------------
// Kernel 5: gemm_partial — fp32 partial C for one K-slice (split-K M-gemm).
// ---------------------------------------------------------------------------
__global__ __launch_bounds__(256, 2) void gemm_partial_kernel(
    const __half* __restrict__ Ah, const __half* __restrict__ Al,
    const __half* __restrict__ Bh, const __half* __restrict__ Bl) {
    extern __shared__ __half sm[];
    const int tid = threadIdx.x, lane = tid & 31, warp = tid >> 5;
    const int wm = warp >> 1, wn = warp & 1;
    const int bm = blockIdx.y * 128, bn = blockIdx.x * 128;
    const int slice = blockIdx.z;

    float acc[2][8][4];
#pragma unroll
    for (int mi = 0; mi < 2; mi++)
#pragma unroll
        for (int ni = 0; ni < 8; ni++)
#pragma unroll
            for (int j = 0; j < 4; j++) acc[mi][ni][j] = 0.f;

    mainloop(sm, Ah, Al, Bh, Bl, bm, bn, slice * (MK_SLABS * KS), MK_SLABS,
             tid, wm, wn, lane, acc);

    float* Cp = g_mp + (size_t)slice * DM * DM;
#pragma unroll
    for (int mi = 0; mi < 2; mi++) {
#pragma unroll
        for (int ni = 0; ni < 8; ni++) {
            int col = bn + wn * 64 + ni * 8 + 2 * (lane & 3);
#pragma unroll
            for (int h = 0; h < 2; h++) {
                int row = bm + wm * 32 + mi * 16 + (lane >> 2) + h * 8;
                *(float2*)(Cp + (size_t)row * DM + col) =
                    make_float2(acc[mi][ni][2 * h + 0], acc[mi][ni][2 * h + 1]);
            }
        }
    }
}

// ---------------------------------------------------------------------------
// Kernel 6: reduce 4 fp32 partials -> M, split to fp16 hi/lo
// ---------------------------------------------------------------------------
__global__ __launch_bounds__(256) void reduce_split_kernel() {
    size_t i = ((size_t)blockIdx.x * 256 + threadIdx.x) * 4;
    float4 a = *(const float4*)(g_mp + i);
    float4 b = *(const float4*)(g_mp + (size_t)DM * DM + i);
    float4 c = *(const float4*)(g_mp + 2 * (size_t)DM * DM + i);
    float4 d = *(const float4*)(g_mp + 3 * (size_t)DM * DM + i);
    float v[4] = {a.x + b.x + c.x + d.x, a.y + b.y + c.y + d.y,
                  a.z + b.z + c.z + d.z, a.w + b.w + c.w + d.w};
    __half hh[4], ll[4];
#pragma unroll
    for (int j = 0; j < 4; j++) {
        hh[j] = __float2half_rn(v[j]);
        ll[j] = __float2half_rn(v[j] - __half2float(hh[j]));
    }
#pragma unroll
    for (int j = 0; j < 2; j++) {
        *(__half2*)(g_mh + i + 2 * j) = __halves2half2(hh[2 * j], hh[2 * j + 1]);
        *(__half2*)(g_ml + i + 2 * j) = __halves2half2(ll[2 * j], ll[2 * j + 1]);
    }
}

// ---------------------------------------------------------------------------
// Kernel 7: gemm_split — C = A-rows . B-rows, epilogue re-splits to fp16 hi/lo.
// Used for T = X2.M^T (grid 8x128).
// ---------------------------------------------------------------------------
__global__ __launch_bounds__(256, 2) void gemm_split_kernel(
    const __half* __restrict__ Ah, const __half* __restrict__ Al,
    const __half* __restrict__ Bh, const __half* __restrict__ Bl,
    __half* __restrict__ Ch, __half* __restrict__ Cl) {
    extern __shared__ __half sm[];
    const int tid = threadIdx.x, lane = tid & 31, warp = tid >> 5;
    const int wm = warp >> 1, wn = warp & 1;
    const int bm = blockIdx.y * 128, bn = blockIdx.x * 128;

    float acc[2][8][4];
#pragma unroll
    for (int mi = 0; mi < 2; mi++)
#pragma unroll
        for (int ni = 0; ni < 8; ni++)
#pragma unroll
            for (int j = 0; j < 4; j++) acc[mi][ni][j] = 0.f;

    mainloop(sm, Ah, Al, Bh, Bl, bm, bn, 0, NSLAB, tid, wm, wn, lane, acc);

#pragma unroll
    for (int mi = 0; mi < 2; mi++) {
#pragma unroll
        for (int ni = 0; ni < 8; ni++) {
            int col = bn + wn * 64 + ni * 8 + 2 * (lane & 3);
#pragma unroll
            for (int h = 0; h < 2; h++) {
                int row = bm + wm * 32 + mi * 16 + (lane >> 2) + h * 8;
                float v0 = acc[mi][ni][2 * h + 0];
                float v1 = acc[mi][ni][2 * h + 1];
                __half h0 = __float2half_rn(v0), h1 = __float2half_rn(v1);
                __half l0 = __float2half_rn(v0 - __half2float(h0));
                __half l1 = __float2half_rn(v1 - __half2float(h1));
                *(__half2*)(Ch + (size_t)row * DM + col) = __halves2half2(h0, h1);
                *(__half2*)(Cl + (size_t)row * DM + col) = __halves2half2(l0, l1);
            }
        }
    }
}

// ---------------------------------------------------------------------------
// Kernel 8: gemm2 — logits[q,k] = X-rows . T-rows per batch -> d_out (fp32)
// ---------------------------------------------------------------------------
__global__ __launch_bounds__(256, 2) void gemm2_kernel(float* __restrict__ out) {
    extern __shared__ __half sm[];
    const int tid = threadIdx.x, lane = tid & 31, warp = tid >> 5;
    const int wm = warp >> 1, wn = warp & 1;
    const int bq = blockIdx.y * 128, bk = blockIdx.x * 128;
    const int bat = blockIdx.z;

    const __half* Ah = g_x1h + (size_t)bat * S_LEN * DM;
    const __half* Al = g_x1l + (size_t)bat * S_LEN * DM;
    const __half* Bh = g_th + (size_t)bat * S_LEN * DM;
    const __half* Bl = g_tl + (size_t)bat * S_LEN * DM;

    float acc[2][8][4];
#pragma unroll
    for (int mi = 0; mi < 2; mi++)
#pragma unroll
        for (int ni = 0; ni < 8; ni++)
#pragma unroll
            for (int j = 0; j < 4; j++) acc[mi][ni][j] = 0.f;

    mainloop(sm, Ah, Al, Bh, Bl, bq, bk, 0, NSLAB, tid, wm, wn, lane, acc);

    float* obase = out + (size_t)bat * S_LEN * S_LEN;
#pragma unroll
    for (int mi = 0; mi < 2; mi++) {
#pragma unroll
        for (int ni = 0; ni < 8; ni++) {
            int col = bk + wn * 64 + ni * 8 + 2 * (lane & 3);
#pragma unroll
            for (int h = 0; h < 2; h++) {
                int row = bq + wm * 32 + mi * 16 + (lane >> 2) + h * 8;
                __stcs((float2*)(obase + (size_t)row * S_LEN + col),
                       make_float2(acc[mi][ni][2 * h + 0], acc[mi][ni][2 * h + 1]));
            }
        }
    }
}

// ---------------------------------------------------------------------------
// Kernel 9: rowwise softmax in place with v2[k] bias, 512 thr/row
// ---------------------------------------------------------------------------
__global__ __launch_bounds__(512) void softmax_kernel(float* __restrict__ out) {
    __shared__ float red[16];
    const int t = threadIdx.x, lane = t & 31, warp = t >> 5;
    const int rowg = blockIdx.x;
    float* p = out + (size_t)rowg * S_LEN;
    const float* v2p = g_v2 + (rowg & ~(S_LEN - 1));  // batch base

    float4 v[2];
#pragma unroll
    for (int i = 0; i < 2; i++) {
        int off = (i * 512 + t) * 4;
        float4 lv = __ldcs((const float4*)(p + off));
        float4 bv = *(const float4*)(v2p + off);
        v[i] = make_float4(lv.x + bv.x, lv.y + bv.y, lv.z + bv.z, lv.w + bv.w);
    }

    float mx = -INFINITY;
#pragma unroll
    for (int i = 0; i < 2; i++)
        mx = fmaxf(mx, fmaxf(fmaxf(v[i].x, v[i].y), fmaxf(v[i].z, v[i].w)));
#pragma unroll
    for (int o = 16; o >= 1; o >>= 1)
        mx = fmaxf(mx, __shfl_xor_sync(0xffffffffu, mx, o));
    if (lane == 0) red[warp] = mx;
    __syncthreads();
    float bmx = red[0];
#pragma unroll
    for (int w = 1; w < 16; w++) bmx = fmaxf(bmx, red[w]);
    __syncthreads();

    float sum = 0.f;
#pragma unroll
    for (int i = 0; i < 2; i++) {
        v[i].x = __expf(v[i].x - bmx); sum += v[i].x;
        v[i].y = __expf(v[i].y - bmx); sum += v[i].y;
        v[i].z = __expf(v[i].z - bmx); sum += v[i].z;
        v[i].w = __expf(v[i].w - bmx); sum += v[i].w;
    }
#pragma unroll
    for (int o = 16; o >= 1; o >>= 1)
        sum += __shfl_xor_sync(0xffffffffu, sum, o);
    if (lane == 0) red[warp] = sum;
    __syncthreads();
    float bsum = 0.f;
#pragma unroll
    for (int w = 0; w < 16; w++) bsum += red[w];

    float inv = 1.0f / bsum;
#pragma unroll
    for (int i = 0; i < 2; i++) {
        v[i].x *= inv; v[i].y *= inv; v[i].z *= inv; v[i].w *= inv;
        __stcs((float4*)(p + (i * 512 + t) * 4), v[i]);
    }
}

// ---------------------------------------------------------------------------
// Launch DAG:
//   main: split_x12 ─[wait s2]→ T-gemm → gemm2 ─[wait s3]→ softmax
//   s2:   split_w → M-partial → reduce
//   s3:   u → v2           (consumed only by softmax)
// ---------------------------------------------------------------------------
extern "C" void kernel_launch(void* const* d_in, const int* in_sizes, int n_in,
                              void* d_out, int out_size) {
    (void)in_sizes; (void)n_in; (void)out_size;
    const float* hidden = (const float*)d_in[0];
    const float* pre    = (const float*)d_in[1];
    const float* w1     = (const float*)d_in[2];
    const float* b1     = (const float*)d_in[3];
    const float* w2     = (const float*)d_in[4];
    const float* b2     = (const float*)d_in[5];
    (void)b2;  // b2 terms are row-constant in softmax -> cancel
    float* out = (float*)d_out;

    static cudaStream_t s2 = nullptr, s3 = nullptr;
    static cudaEvent_t ev_fork = nullptr, ev_m = nullptr, ev_v2 = nullptr;
    if (s2 == nullptr) {
        cudaStreamCreateWithFlags(&s2, cudaStreamNonBlocking);
        cudaStreamCreateWithFlags(&s3, cudaStreamNonBlocking);
        cudaEventCreateWithFlags(&ev_fork, cudaEventDisableTiming);
        cudaEventCreateWithFlags(&ev_m, cudaEventDisableTiming);
        cudaEventCreateWithFlags(&ev_v2, cudaEventDisableTiming);
    }

    cudaFuncSetAttribute(gemm_partial_kernel,
                         cudaFuncAttributeMaxDynamicSharedMemorySize, GEMM_SMEM);
    cudaFuncSetAttribute(gemm_split_kernel,
                         cudaFuncAttributeMaxDynamicSharedMemorySize, GEMM_SMEM);
    cudaFuncSetAttribute(gemm2_kernel,
                         cudaFuncAttributeMaxDynamicSharedMemorySize, GEMM_SMEM);

    __half *x2h, *x2l, *w1h, *w1l, *w2h, *w2l, *mh, *ml, *th, *tl;
    cudaGetSymbolAddress((void**)&x2h, g_x2h);
    cudaGetSymbolAddress((void**)&x2l, g_x2l);
    cudaGetSymbolAddress((void**)&w1h, g_w1h);
    cudaGetSymbolAddress((void**)&w1l, g_w1l);
    cudaGetSymbolAddress((void**)&w2h, g_w2h);
    cudaGetSymbolAddress((void**)&w2l, g_w2l);
    cudaGetSymbolAddress((void**)&mh, g_mh);
    cudaGetSymbolAddress((void**)&ml, g_ml);
    cudaGetSymbolAddress((void**)&th, g_th);
    cudaGetSymbolAddress((void**)&tl, g_tl);

    // Fork side streams.
    cudaEventRecord(ev_fork, 0);
    cudaStreamWaitEvent(s2, ev_fork, 0);
    cudaStreamWaitEvent(s3, ev_fork, 0);

    // s2: weight split + M chain.
    split_w_kernel<<<(DM * DM) / (256 * 4), 256, 0, s2>>>(w1, w2);
    gemm_partial_kernel<<<dim3(DM / 128, DM / 128, MK_SLICES), 256, GEMM_SMEM, s2>>>(
        w1h, w1l, w2h, w2l);
    reduce_split_kernel<<<(DM * DM) / (256 * 4), 256, 0, s2>>>();
    cudaEventRecord(ev_m, s2);

    // s3: u -> v2 (softmax-only; overlaps the T-gemm).
    u_kernel<<<DM / 8, 256, 0, s3>>>(w2, b1);
    v2_kernel<<<MTOT / 8, 256, 0, s3>>>(hidden, pre);
    cudaEventRecord(ev_v2, s3);

    // main: fused x1+x2 split (starts immediately; no u dependency).
    split_x12_kernel<<<(MTOT * DM) / (256 * 4), 256>>>(hidden, pre);

    // Join M; T[k,d] = X2 rows . M rows.
    cudaStreamWaitEvent(0, ev_m, 0);
    gemm_split_kernel<<<dim3(DM / 128, MTOT / 128), 256, GEMM_SMEM>>>(
        x2h, x2l, mh, ml, th, tl);

    // logits; then join v2 before softmax.
    gemm2_kernel<<<dim3(S_LEN / 128, S_LEN / 128, BATCH), 256, GEMM_SMEM>>>(out);
    cudaStreamWaitEvent(0, ev_v2, 0);
    softmax_kernel<<<MTOT, 512>>>(out);
}

// round 15
// speedup vs baseline: 1.0203x; 1.0151x over previous
#include <cuda_runtime.h>
#include <cuda_fp16.h>
#include <math.h>
#include <stdint.h>

// Problem constants
#define S_LEN 4096
#define BATCH 4
#define DM    1024
#define MTOT  (BATCH * S_LEN)

#define KS     32
#define NSLAB  (DM / KS)       // 32
#define APITCH 40              // smem row pitch in halves (+8 pad)

// All GEMMs: CTA 128x128, 256 thr (8 warps, 4m x 2n), warp 32x64, 2 CTA/SM.
#define STG_HALVES ((256 + 256) * APITCH)          // 20480
#define GEMM_SMEM  (2 * STG_HALVES * 2)            // 81920 B

#define MK_SLICES 4
#define MK_SLABS  (NSLAB / MK_SLICES)              // 8 slabs per K-slice

// ---------------------------------------------------------------------------
// Scratch (device globals)
// ---------------------------------------------------------------------------
__device__ __half g_x1h[(size_t)MTOT * DM];   // hidden split
__device__ __half g_x1l[(size_t)MTOT * DM];
__device__ __half g_x2h[(size_t)MTOT * DM];   // hidden+pre split
__device__ __half g_x2l[(size_t)MTOT * DM];
__device__ __half g_w1h[(size_t)DM * DM];     // w1 split, row-major [d][e]
__device__ __half g_w1l[(size_t)DM * DM];
__device__ __half g_w2h[(size_t)DM * DM];     // w2 split, row-major [d][e]
__device__ __half g_w2l[(size_t)DM * DM];
__device__ float  g_mp[(size_t)MK_SLICES * DM * DM];  // M split-K partials
__device__ __half g_mh[(size_t)DM * DM];      // M = w1 w2^T split, [d][d']
__device__ __half g_ml[(size_t)DM * DM];
__device__ __half g_th[(size_t)MTOT * DM];    // T = X2 M^T split, [k][d]
__device__ __half g_tl[(size_t)MTOT * DM];
__device__ float  g_u[DM];                    // u = w2 b1
__device__ float  g_v2[MTOT];                 // v2 = (hidden+pre) . u

// ---------------------------------------------------------------------------
// PTX helpers
// ---------------------------------------------------------------------------
__device__ __forceinline__ uint32_t smem_u32(const void* p) {
    return (uint32_t)__cvta_generic_to_shared(p);
}
__device__ __forceinline__ void ldsm4(uint32_t addr, uint32_t& r0, uint32_t& r1,
                                      uint32_t& r2, uint32_t& r3) {
    asm volatile("ldmatrix.sync.aligned.m8n8.x4.shared.b16 {%0,%1,%2,%3}, [%4];\n"
                 : "=r"(r0), "=r"(r1), "=r"(r2), "=r"(r3) : "r"(addr));
}
__device__ __forceinline__ void mma16816(float c[4], const uint32_t a[4],
                                         uint32_t b0, uint32_t b1) {
    asm volatile(
        "mma.sync.aligned.m16n8k16.row.col.f32.f16.f16.f32 "
        "{%0,%1,%2,%3}, {%4,%5,%6,%7}, {%8,%9}, {%0,%1,%2,%3};\n"
        : "+f"(c[0]), "+f"(c[1]), "+f"(c[2]), "+f"(c[3])
        : "r"(a[0]), "r"(a[1]), "r"(a[2]), "r"(a[3]), "r"(b0), "r"(b1));
}
__device__ __forceinline__ void cp16(void* sdst, const void* gsrc) {
    uint32_t s = smem_u32(sdst);
    asm volatile("cp.async.cg.shared.global [%0], [%1], 16;\n" :: "r"(s), "l"(gsrc));
}
#define CP_COMMIT() asm volatile("cp.async.commit_group;\n" ::: "memory")
#define CP_WAIT1()  asm volatile("cp.async.wait_group 1;\n" ::: "memory")
#define CP_WAIT0()  asm volatile("cp.async.wait_group 0;\n" ::: "memory")

// ---------------------------------------------------------------------------
// Kernel 1: u[d] = sum_e w2[d,e] * b1[e]   (warp per row)
// ---------------------------------------------------------------------------
__global__ __launch_bounds__(256) void u_kernel(
    const float* __restrict__ w2, const float* __restrict__ b1) {
    const int warp = threadIdx.x >> 5, lane = threadIdx.x & 31;
    const int row = blockIdx.x * 8 + warp;
    const float* p = w2 + (size_t)row * DM;
    float s = 0.f;
#pragma unroll
    for (int j = 0; j < DM / 32; j++) s += p[lane + 32 * j] * b1[lane + 32 * j];
#pragma unroll
    for (int o = 16; o >= 1; o >>= 1) s += __shfl_xor_sync(0xffffffffu, s, o);
    if (lane == 0) g_u[row] = s;
}

// ---------------------------------------------------------------------------
// Kernel 2: split hidden / hidden+pre into fp16 hi/lo AND v2[row] = x2 . u.
// One block per row. x1 outputs use streaming stores (consumed much later
// by gemm2; keeps L2 clean for x2 + M during the T-gemm).
// ---------------------------------------------------------------------------
__global__ __launch_bounds__(256) void split_x_kernel(
    const float* __restrict__ hidden, const float* __restrict__ pre) {
    __shared__ float red[8];
    const int row = blockIdx.x, t = threadIdx.x;
    const int lane = t & 31, warp = t >> 5;
    size_t i = (size_t)row * DM + t * 4;

    float4 hv = *(const float4*)(hidden + i);
    float4 pv = *(const float4*)(pre + i);
    float4 uv = *(const float4*)(g_u + t * 4);
    float x1[4] = {hv.x, hv.y, hv.z, hv.w};
    float x2[4] = {hv.x + pv.x, hv.y + pv.y, hv.z + pv.z, hv.w + pv.w};
    float dot = x2[0] * uv.x + x2[1] * uv.y + x2[2] * uv.z + x2[3] * uv.w;

    __half h1[4], l1[4], h2[4], l2[4];
#pragma unroll
    for (int j = 0; j < 4; j++) {
        h1[j] = __float2half_rn(x1[j]);
        l1[j] = __float2half_rn(x1[j] - __half2float(h1[j]));
        h2[j] = __float2half_rn(x2[j]);
        l2[j] = __float2half_rn(x2[j] - __half2float(h2[j]));
    }
    // x1: streaming 8B stores (packed 4 halves)
    {
        __half2 a0 = __halves2half2(h1[0], h1[1]), a1 = __halves2half2(h1[2], h1[3]);
        __half2 b0 = __halves2half2(l1[0], l1[1]), b1 = __halves2half2(l1[2], l1[3]);
        float2 fh = make_float2(__uint_as_float(*(uint32_t*)&a0),
                                __uint_as_float(*(uint32_t*)&a1));
        float2 fl = make_float2(__uint_as_float(*(uint32_t*)&b0),
                                __uint_as_float(*(uint32_t*)&b1));
        __stcs((float2*)(g_x1h + i), fh);
        __stcs((float2*)(g_x1l + i), fl);
    }
    // x2: default stores (hot input of the immediately-following T-gemm)
#pragma unroll
    for (int j = 0; j < 2; j++) {
        *(__half2*)(g_x2h + i + 2 * j) = __halves2half2(h2[2 * j], h2[2 * j + 1]);
        *(__half2*)(g_x2l + i + 2 * j) = __halves2half2(l2[2 * j], l2[2 * j + 1]);
    }

#pragma unroll
    for (int o = 16; o >= 1; o >>= 1) dot += __shfl_xor_sync(0xffffffffu, dot, o);
    if (lane == 0) red[warp] = dot;
    __syncthreads();
    if (t == 0) {
        float s = 0.f;
#pragma unroll
        for (int w = 0; w < 8; w++) s += red[w];
        g_v2[row] = s;
    }
}

// ---------------------------------------------------------------------------
// Kernel 3: elementwise split of w1, w2 (row-major, no transpose)
// ---------------------------------------------------------------------------
__global__ __launch_bounds__(256) void split_w_kernel(
    const float* __restrict__ w1, const float* __restrict__ w2) {
    size_t i = ((size_t)blockIdx.x * 256 + threadIdx.x) * 4;
    float4 v1 = *(const float4*)(w1 + i);
    float4 v2 = *(const float4*)(w2 + i);
    float a1[4] = {v1.x, v1.y, v1.z, v1.w};
    float a2[4] = {v2.x, v2.y, v2.z, v2.w};
#pragma unroll
    for (int j = 0; j < 4; j++) {
        __half h1 = __float2half_rn(a1[j]);
        __half h2 = __float2half_rn(a2[j]);
        g_w1h[i + j] = h1; g_w1l[i + j] = __float2half_rn(a1[j] - __half2float(h1));
        g_w2h[i + j] = h2; g_w2l[i + j] = __float2half_rn(a2[j] - __half2float(h2));
    }
}

// ---------------------------------------------------------------------------
// Shared rows-x-rows mainloop: acc[2][8][4] += split-fp16 x3 of
//   C[m,n] = sum_{k in [kbeg, kbeg+kcnt*KS)} A[bm+m, k] * B[bn+n, k]
// ---------------------------------------------------------------------------
__device__ __forceinline__ void mainloop(
    __half* sm, const __half* __restrict__ Ah, const __half* __restrict__ Al,
    const __half* __restrict__ Bh, const __half* __restrict__ Bl,
    int bm, int bn, int kbeg, int kcnt,
    int tid, int wm, int wn, int lane, float acc[2][8][4])
{
    constexpr int ST_AH = 0;
    constexpr int ST_AL = 128 * APITCH;
    constexpr int ST_BH = 256 * APITCH;
    constexpr int ST_BL = 384 * APITCH;

    auto load_slab = [&](int k0, int s) {
        __half* stg = sm + s * STG_HALVES;
#pragma unroll
        for (int t = 0; t < 2; t++) {
            int slot = tid + t * 256;
            int row = slot >> 2, cg = slot & 3;
            int so = row * APITCH + cg * 8;
            size_t ga = (size_t)(bm + row) * DM + k0 + cg * 8;
            size_t gb = (size_t)(bn + row) * DM + k0 + cg * 8;
            cp16(stg + ST_AH + so, Ah + ga);
            cp16(stg + ST_AL + so, Al + ga);
            cp16(stg + ST_BH + so, Bh + gb);
            cp16(stg + ST_BL + so, Bl + gb);
        }
        CP_COMMIT();
    };

    load_slab(kbeg, 0);

    for (int i = 0; i < kcnt; i++) {
        const int s = i & 1;
        if (i + 1 < kcnt) { load_slab(kbeg + (i + 1) * KS, s ^ 1); CP_WAIT1(); }
        else              { CP_WAIT0(); }
        __syncthreads();

        const __half* stg = sm + s * STG_HALVES;
        const __half* sAh = stg + ST_AH;
        const __half* sAl = stg + ST_AL;
        const __half* sBh = stg + ST_BH;
        const __half* sBl = stg + ST_BL;
        const int g = lane >> 3;

#pragma unroll
        for (int kk = 0; kk < KS; kk += 16) {
            const int col = kk + (g >> 1) * 8;
            uint32_t ah[2][4], al[2][4];
#pragma unroll
            for (int mi = 0; mi < 2; mi++) {
                int row = wm * 32 + mi * 16 + (lane & 7) + (g & 1) * 8;
                ldsm4(smem_u32(sAh + row * APITCH + col),
                      ah[mi][0], ah[mi][1], ah[mi][2], ah[mi][3]);
                ldsm4(smem_u32(sAl + row * APITCH + col),
                      al[mi][0], al[mi][1], al[mi][2], al[mi][3]);
            }
            uint32_t bh[4][4];
#pragma unroll
            for (int ng = 0; ng < 4; ng++) {
                int row = wn * 64 + ng * 16 + (lane & 7) + (g & 1) * 8;
                ldsm4(smem_u32(sBh + row * APITCH + col),
                      bh[ng][0], bh[ng][1], bh[ng][2], bh[ng][3]);
            }
#pragma unroll
            for (int ng = 0; ng < 4; ng++)
#pragma unroll
                for (int mi = 0; mi < 2; mi++) {
                    mma16816(acc[mi][2 * ng],     ah[mi], bh[ng][0], bh[ng][2]);
                    mma16816(acc[mi][2 * ng + 1], ah[mi], bh[ng][1], bh[ng][3]);
                }
#pragma unroll
            for (int ng = 0; ng < 4; ng++)
#pragma unroll
                for (int mi = 0; mi < 2; mi++) {
                    mma16816(acc[mi][2 * ng],     al[mi], bh[ng][0], bh[ng][2]);
                    mma16816(acc[mi][2 * ng + 1], al[mi], bh[ng][1], bh[ng][3]);
                }
#pragma unroll
            for (int ng = 0; ng < 4; ng++) {
                int row = wn * 64 + ng * 16 + (lane & 7) + (g & 1) * 8;
                uint32_t r0, r1, r2, r3;
                ldsm4(smem_u32(sBl + row * APITCH + col), r0, r1, r2, r3);
#pragma unroll
                for (int mi = 0; mi < 2; mi++) {
                    mma16816(acc[mi][2 * ng],     ah[mi], r0, r2);
                    mma16816(acc[mi][2 * ng + 1], ah[mi], r1, r3);
                }
            }
        }
        __syncthreads();
    }
}

// ---------------------------------------------------------------------------
// Kernel 4: gemm_partial — fp32 partial C for one K-slice (split-K M-gemm).
// ---------------------------------------------------------------------------
__global__ __launch_bounds__(256, 2) void gemm_partial_kernel(
    const __half* __restrict__ Ah, const __half* __restrict__ Al,
    const __half* __restrict__ Bh, const __half* __restrict__ Bl) {
    extern __shared__ __half sm[];
    const int tid = threadIdx.x, lane = tid & 31, warp = tid >> 5;
    const int wm = warp >> 1, wn = warp & 1;
    const int bm = blockIdx.y * 128, bn = blockIdx.x * 128;
    const int slice = blockIdx.z;

    float acc[2][8][4];
#pragma unroll
    for (int mi = 0; mi < 2; mi++)
#pragma unroll
        for (int ni = 0; ni < 8; ni++)
#pragma unroll
            for (int j = 0; j < 4; j++) acc[mi][ni][j] = 0.f;

    mainloop(sm, Ah, Al, Bh, Bl, bm, bn, slice * (MK_SLABS * KS), MK_SLABS,
             tid, wm, wn, lane, acc);

    float* Cp = g_mp + (size_t)slice * DM * DM;
#pragma unroll
    for (int mi = 0; mi < 2; mi++) {
#pragma unroll
        for (int ni = 0; ni < 8; ni++) {
            int col = bn + wn * 64 + ni * 8 + 2 * (lane & 3);
#pragma unroll
            for (int h = 0; h < 2; h++) {
                int row = bm + wm * 32 + mi * 16 + (lane >> 2) + h * 8;
                *(float2*)(Cp + (size_t)row * DM + col) =
                    make_float2(acc[mi][ni][2 * h + 0], acc[mi][ni][2 * h + 1]);
            }
        }
    }
}

// ---------------------------------------------------------------------------
// Kernel 5: reduce 4 fp32 partials -> M, split to fp16 hi/lo
// ---------------------------------------------------------------------------
__global__ __launch_bounds__(256) void reduce_split_kernel() {
    size_t i = ((size_t)blockIdx.x * 256 + threadIdx.x) * 4;
    float4 a = *(const float4*)(g_mp + i);
    float4 b = *(const float4*)(g_mp + (size_t)DM * DM + i);
    float4 c = *(const float4*)(g_mp + 2 * (size_t)DM * DM + i);
    float4 d = *(const float4*)(g_mp + 3 * (size_t)DM * DM + i);
    float v[4] = {a.x + b.x + c.x + d.x, a.y + b.y + c.y + d.y,
                  a.z + b.z + c.z + d.z, a.w + b.w + c.w + d.w};
    __half hh[4], ll[4];
#pragma unroll
    for (int j = 0; j < 4; j++) {
        hh[j] = __float2half_rn(v[j]);
        ll[j] = __float2half_rn(v[j] - __half2float(hh[j]));
    }
#pragma unroll
    for (int j = 0; j < 2; j++) {
        *(__half2*)(g_mh + i + 2 * j) = __halves2half2(hh[2 * j], hh[2 * j + 1]);
        *(__half2*)(g_ml + i + 2 * j) = __halves2half2(ll[2 * j], ll[2 * j + 1]);
    }
}

// ---------------------------------------------------------------------------
// Kernel 6: gemm_split — C = A-rows . B-rows, epilogue re-splits to fp16 hi/lo.
// Used for T = X2.M^T (grid 8x128).
// ---------------------------------------------------------------------------
__global__ __launch_bounds__(256, 2) void gemm_split_kernel(
    const __half* __restrict__ Ah, const __half* __restrict__ Al,
    const __half* __restrict__ Bh, const __half* __restrict__ Bl,
    __half* __restrict__ Ch, __half* __restrict__ Cl) {
    extern __shared__ __half sm[];
    const int tid = threadIdx.x, lane = tid & 31, warp = tid >> 5;
    const int wm = warp >> 1, wn = warp & 1;
    const int bm = blockIdx.y * 128, bn = blockIdx.x * 128;

    float acc[2][8][4];
#pragma unroll
    for (int mi = 0; mi < 2; mi++)
#pragma unroll
        for (int ni = 0; ni < 8; ni++)
#pragma unroll
            for (int j = 0; j < 4; j++) acc[mi][ni][j] = 0.f;

    mainloop(sm, Ah, Al, Bh, Bl, bm, bn, 0, NSLAB, tid, wm, wn, lane, acc);

#pragma unroll
    for (int mi = 0; mi < 2; mi++) {
#pragma unroll
        for (int ni = 0; ni < 8; ni++) {
            int col = bn + wn * 64 + ni * 8 + 2 * (lane & 3);
#pragma unroll
            for (int h = 0; h < 2; h++) {
                int row = bm + wm * 32 + mi * 16 + (lane >> 2) + h * 8;
                float v0 = acc[mi][ni][2 * h + 0];
                float v1 = acc[mi][ni][2 * h + 1];
                __half h0 = __float2half_rn(v0), h1 = __float2half_rn(v1);
                __half l0 = __float2half_rn(v0 - __half2float(h0));
                __half l1 = __float2half_rn(v1 - __half2float(h1));
                *(__half2*)(Ch + (size_t)row * DM + col) = __halves2half2(h0, h1);
                *(__half2*)(Cl + (size_t)row * DM + col) = __halves2half2(l0, l1);
            }
        }
    }
}

// ---------------------------------------------------------------------------
// Kernel 7: gemm2 — logits[q,k] = X-rows . T-rows per batch -> d_out (fp32)
// ---------------------------------------------------------------------------
__global__ __launch_bounds__(256, 2) void gemm2_kernel(float* __restrict__ out) {
    extern __shared__ __half sm[];
    const int tid = threadIdx.x, lane = tid & 31, warp = tid >> 5;
    const int wm = warp >> 1, wn = warp & 1;
    const int bq = blockIdx.y * 128, bk = blockIdx.x * 128;
    const int bat = blockIdx.z;

    const __half* Ah = g_x1h + (size_t)bat * S_LEN * DM;
    const __half* Al = g_x1l + (size_t)bat * S_LEN * DM;
    const __half* Bh = g_th + (size_t)bat * S_LEN * DM;
    const __half* Bl = g_tl + (size_t)bat * S_LEN * DM;

    float acc[2][8][4];
#pragma unroll
    for (int mi = 0; mi < 2; mi++)
#pragma unroll
        for (int ni = 0; ni < 8; ni++)
#pragma unroll
            for (int j = 0; j < 4; j++) acc[mi][ni][j] = 0.f;

    mainloop(sm, Ah, Al, Bh, Bl, bq, bk, 0, NSLAB, tid, wm, wn, lane, acc);

    float* obase = out + (size_t)bat * S_LEN * S_LEN;
#pragma unroll
    for (int mi = 0; mi < 2; mi++) {
#pragma unroll
        for (int ni = 0; ni < 8; ni++) {
            int col = bk + wn * 64 + ni * 8 + 2 * (lane & 3);
#pragma unroll
            for (int h = 0; h < 2; h++) {
                int row = bq + wm * 32 + mi * 16 + (lane >> 2) + h * 8;
                __stcs((float2*)(obase + (size_t)row * S_LEN + col),
                       make_float2(acc[mi][ni][2 * h + 0], acc[mi][ni][2 * h + 1]));
            }
        }
    }
}

// ---------------------------------------------------------------------------
// Kernel 8: rowwise softmax in place with v2[k] bias, streaming ld/st
// ---------------------------------------------------------------------------
__global__ __launch_bounds__(256) void softmax_kernel(float* __restrict__ out) {
    __shared__ float red[8];
    const int t = threadIdx.x, lane = t & 31, warp = t >> 5;
    const int rowg = blockIdx.x;
    float* p = out + (size_t)rowg * S_LEN;
    const float* v2p = g_v2 + (rowg & ~(S_LEN - 1));  // batch base

    float4 v[4];
#pragma unroll
    for (int i = 0; i < 4; i++) {
        int off = (i * 256 + t) * 4;
        float4 lv = __ldcs((const float4*)(p + off));
        float4 bv = *(const float4*)(v2p + off);
        v[i] = make_float4(lv.x + bv.x, lv.y + bv.y, lv.z + bv.z, lv.w + bv.w);
    }

    float mx = -INFINITY;
#pragma unroll
    for (int i = 0; i < 4; i++)
        mx = fmaxf(mx, fmaxf(fmaxf(v[i].x, v[i].y), fmaxf(v[i].z, v[i].w)));
#pragma unroll
    for (int o = 16; o >= 1; o >>= 1)
        mx = fmaxf(mx, __shfl_xor_sync(0xffffffffu, mx, o));
    if (lane == 0) red[warp] = mx;
    __syncthreads();
    float bmx = red[0];
#pragma unroll
    for (int w = 1; w < 8; w++) bmx = fmaxf(bmx, red[w]);
    __syncthreads();

    float sum = 0.f;
#pragma unroll
    for (int i = 0; i < 4; i++) {
        v[i].x = __expf(v[i].x - bmx); sum += v[i].x;
        v[i].y = __expf(v[i].y - bmx); sum += v[i].y;
        v[i].z = __expf(v[i].z - bmx); sum += v[i].z;
        v[i].w = __expf(v[i].w - bmx); sum += v[i].w;
    }
#pragma unroll
    for (int o = 16; o >= 1; o >>= 1)
        sum += __shfl_xor_sync(0xffffffffu, sum, o);
    if (lane == 0) red[warp] = sum;
    __syncthreads();
    float bsum = 0.f;
#pragma unroll
    for (int w = 0; w < 8; w++) bsum += red[w];

    float inv = 1.0f / bsum;
#pragma unroll
    for (int i = 0; i < 4; i++) {
        v[i].x *= inv; v[i].y *= inv; v[i].z *= inv; v[i].w *= inv;
        __stcs((float4*)(p + (i * 256 + t) * 4), v[i]);
    }
}

// ---------------------------------------------------------------------------
// Launch DAG (R12 winner):
//   main: u → split_x ─[wait s2]→ T-gemm → gemm2 → softmax
//   s2:   split_w → M-partial → reduce
// ---------------------------------------------------------------------------
extern "C" void kernel_launch(void* const* d_in, const int* in_sizes, int n_in,
                              void* d_out, int out_size) {
    (void)in_sizes; (void)n_in; (void)out_size;
    const float* hidden = (const float*)d_in[0];
    const float* pre    = (const float*)d_in[1];
    const float* w1     = (const float*)d_in[2];
    const float* b1     = (const float*)d_in[3];
    const float* w2     = (const float*)d_in[4];
    const float* b2     = (const float*)d_in[5];
    (void)b2;  // b2 terms are row-constant in softmax -> cancel
    float* out = (float*)d_out;

    static cudaStream_t s2 = nullptr;
    static cudaEvent_t ev_fork = nullptr, ev_m = nullptr;
    if (s2 == nullptr) {
        cudaStreamCreateWithFlags(&s2, cudaStreamNonBlocking);
        cudaEventCreateWithFlags(&ev_fork, cudaEventDisableTiming);
        cudaEventCreateWithFlags(&ev_m, cudaEventDisableTiming);
    }

    cudaFuncSetAttribute(gemm_partial_kernel,
                         cudaFuncAttributeMaxDynamicSharedMemorySize, GEMM_SMEM);
    cudaFuncSetAttribute(gemm_split_kernel,
                         cudaFuncAttributeMaxDynamicSharedMemorySize, GEMM_SMEM);
    cudaFuncSetAttribute(gemm2_kernel,
                         cudaFuncAttributeMaxDynamicSharedMemorySize, GEMM_SMEM);

    __half *x2h, *x2l, *w1h, *w1l, *w2h, *w2l, *mh, *ml, *th, *tl;
    cudaGetSymbolAddress((void**)&x2h, g_x2h);
    cudaGetSymbolAddress((void**)&x2l, g_x2l);
    cudaGetSymbolAddress((void**)&w1h, g_w1h);
    cudaGetSymbolAddress((void**)&w1l, g_w1l);
    cudaGetSymbolAddress((void**)&w2h, g_w2h);
    cudaGetSymbolAddress((void**)&w2l, g_w2l);
    cudaGetSymbolAddress((void**)&mh, g_mh);
    cudaGetSymbolAddress((void**)&ml, g_ml);
    cudaGetSymbolAddress((void**)&th, g_th);
    cudaGetSymbolAddress((void**)&tl, g_tl);

    // Fork: side stream handles weight split + M chain (independent of x data).
    cudaEventRecord(ev_fork, 0);
    cudaStreamWaitEvent(s2, ev_fork, 0);

    split_w_kernel<<<(DM * DM) / (256 * 4), 256, 0, s2>>>(w1, w2);
    gemm_partial_kernel<<<dim3(DM / 128, DM / 128, MK_SLICES), 256, GEMM_SMEM, s2>>>(
        w1h, w1l, w2h, w2l);
    reduce_split_kernel<<<(DM * DM) / (256 * 4), 256, 0, s2>>>();
    cudaEventRecord(ev_m, s2);

    // Main stream: u (needed by split_x) then fused x split + v2 fold.
    u_kernel<<<DM / 8, 256>>>(w2, b1);
    split_x_kernel<<<MTOT, 256>>>(hidden, pre);

    // Join: T-gemm needs both M (s2) and x2 (main).
    cudaStreamWaitEvent(0, ev_m, 0);

    // T[k,d] = X2 rows . M rows (dot over d')
    gemm_split_kernel<<<dim3(DM / 128, MTOT / 128), 256, GEMM_SMEM>>>(
        x2h, x2l, mh, ml, th, tl);
    // logits[q,k] = X rows . T rows (dot over d), per batch
    gemm2_kernel<<<dim3(S_LEN / 128, S_LEN / 128, BATCH), 256, GEMM_SMEM>>>(out);
    softmax_kernel<<<MTOT, 256>>>(out);
}